// round 1
// baseline (speedup 1.0000x reference)
#include <cuda_runtime.h>
#include <cuda_bf16.h>
#include <math.h>

// Problem constants
#define BB   256
#define TT   256
#define II   256
#define HH   1024
#define KTOT 1280           // I + H
#define NG   4096           // 4*H
#define TAUc 0.05f
#define MHUc 1.5f

#define BTH  ((long)BB * TT * HH)
#define BH   ((long)BB * HH)

// Persistent device scratch (static __device__ arrays: allocation-free)
__device__ float g_Wt[(long)NG * KTOT];   // permuted, tf32-rounded weights (N-major, K contiguous)
__device__ float g_h[2][BB * HH];         // double-buffered hidden carry (with ODE transform applied)
__device__ float g_c[BB * HH];            // cell state

// ---------------------------------------------------------------------------
// Column permutation: permuted column n' -> (gate, hcol)
//   gate(n') = (n' >> 3) & 3
//   hcol(n') = (n'>>6)*16 + ((n'>>5)&1)*8 + (n'&7)
// This makes every warp's 32-col tile = {4 gates} x {8 h-cols}.
// ---------------------------------------------------------------------------

__global__ void transform_W(const float* __restrict__ Wx, const float* __restrict__ Wh) {
    long idx = (long)blockIdx.x * blockDim.x + threadIdx.x;
    if (idx >= (long)NG * KTOT) return;
    int k = (int)(idx % KTOT);
    int n = (int)(idx / KTOT);
    int gate = (n >> 3) & 3;
    int hcol = ((n >> 6) << 4) | (((n >> 5) & 1) << 3) | (n & 7);
    int col  = gate * HH + hcol;
    float v = (k < II) ? Wx[(long)k * NG + col] : Wh[(long)(k - II) * NG + col];
    unsigned u;
    asm("cvt.rna.tf32.f32 %0, %1;" : "=r"(u) : "f"(v));   // round once, bias-free
    g_Wt[idx] = __uint_as_float(u);
}

__global__ void init_state(const float* __restrict__ h0, const float* __restrict__ c0) {
    int idx = blockIdx.x * blockDim.x + threadIdx.x;
    if (idx < BB * HH) {
        g_h[0][idx] = h0[idx];
        g_c[idx]    = c0[idx];
    }
}

__device__ __forceinline__ unsigned f2tf32(float v) {
    unsigned u;
    asm("cvt.rna.tf32.f32 %0, %1;" : "=r"(u) : "f"(v));
    return u;
}

__device__ __forceinline__ void mma_tf32(float* d, const unsigned* a, const unsigned* b) {
    asm volatile(
        "mma.sync.aligned.m16n8k8.row.col.f32.tf32.tf32.f32 "
        "{%0,%1,%2,%3}, {%4,%5,%6,%7}, {%8,%9}, {%0,%1,%2,%3};"
        : "+f"(d[0]), "+f"(d[1]), "+f"(d[2]), "+f"(d[3])
        : "r"(a[0]), "r"(a[1]), "r"(a[2]), "r"(a[3]), "r"(b[0]), "r"(b[1]));
}

__device__ __forceinline__ float sigf(float x) { return 1.0f / (1.0f + expf(-x)); }

// ---------------------------------------------------------------------------
// Per-step fused kernel: gates = [u_t, h] @ Wt' + b  -> LSTM epilogue
// Grid: (64 N-tiles, 2 M-tiles), 256 threads (8 warps, 4x2 warp grid of 32x32)
// ---------------------------------------------------------------------------
#define BK 16
#define NKT (KTOT / BK)   // 80

__global__ void __launch_bounds__(256, 1)
lstm_step(const float* __restrict__ x,      // rnn_input (B,T,I)
          const float* __restrict__ bias,   // (4H,)
          float* __restrict__ out,          // outputs | hN | cN
          int t, int srcbuf)
{
    const float* __restrict__ hsrc = g_h[srcbuf];
    float* __restrict__ hdst = g_h[srcbuf ^ 1];

    __shared__ float As[2][128 * 17];
    __shared__ float Bs[2][64 * 17];

    const int tid    = threadIdx.x;
    const int lane   = tid & 31;
    const int warp   = tid >> 5;
    const int warp_m = warp >> 1;        // 0..3
    const int warp_n = warp & 1;         // 0..1
    const int ctan   = blockIdx.x;       // 0..63
    const int mtile  = blockIdx.y;       // 0..1

    float acc[2][4][4];
    #pragma unroll
    for (int a = 0; a < 2; a++)
        #pragma unroll
        for (int bq = 0; bq < 4; bq++)
            #pragma unroll
            for (int c = 0; c < 4; c++) acc[a][bq][c] = 0.0f;

    // global-load lambdas ---------------------------------------------------
    // A tile: 128 rows x 16 k  -> 512 float4, 2 per thread
    // B tile: 64 rows x 16 k   -> 256 float4, 1 per thread
    const int a_row0 = (tid + 0)   >> 2, a_ko0 = ((tid + 0)   & 3) * 4;
    const int a_row1 = (tid + 256) >> 2, a_ko1 = ((tid + 256) & 3) * 4;
    const int b_row  = tid >> 2,         b_ko  = (tid & 3) * 4;

    float4 ra0, ra1, rb;

    auto ldg_tile = [&](int kt) {
        int kg0 = kt * BK + a_ko0;
        int kg1 = kt * BK + a_ko1;
        int bg0 = mtile * 128 + a_row0;
        int bg1 = mtile * 128 + a_row1;
        if (kg0 < II) {
            ra0 = *(const float4*)(x + ((long)bg0 * TT + t) * II + kg0);
            ra1 = *(const float4*)(x + ((long)bg1 * TT + t) * II + kg1);
        } else {
            ra0 = *(const float4*)(hsrc + (long)bg0 * HH + (kg0 - II));
            ra1 = *(const float4*)(hsrc + (long)bg1 * HH + (kg1 - II));
        }
        rb = *(const float4*)(g_Wt + (long)(ctan * 64 + b_row) * KTOT + kt * BK + b_ko);
    };

    auto sts_tile = [&](int buf) {
        float* A = As[buf];
        float* Bsm = Bs[buf];
        A[a_row0 * 17 + a_ko0 + 0] = __uint_as_float(f2tf32(ra0.x));
        A[a_row0 * 17 + a_ko0 + 1] = __uint_as_float(f2tf32(ra0.y));
        A[a_row0 * 17 + a_ko0 + 2] = __uint_as_float(f2tf32(ra0.z));
        A[a_row0 * 17 + a_ko0 + 3] = __uint_as_float(f2tf32(ra0.w));
        A[a_row1 * 17 + a_ko1 + 0] = __uint_as_float(f2tf32(ra1.x));
        A[a_row1 * 17 + a_ko1 + 1] = __uint_as_float(f2tf32(ra1.y));
        A[a_row1 * 17 + a_ko1 + 2] = __uint_as_float(f2tf32(ra1.z));
        A[a_row1 * 17 + a_ko1 + 3] = __uint_as_float(f2tf32(ra1.w));
        Bsm[b_row * 17 + b_ko + 0] = rb.x;   // Wt already tf32-rounded
        Bsm[b_row * 17 + b_ko + 1] = rb.y;
        Bsm[b_row * 17 + b_ko + 2] = rb.z;
        Bsm[b_row * 17 + b_ko + 3] = rb.w;
    };

    // prologue
    ldg_tile(0);
    sts_tile(0);
    __syncthreads();

    // main K loop -----------------------------------------------------------
    for (int kt = 0; kt < NKT; kt++) {
        if (kt + 1 < NKT) ldg_tile(kt + 1);

        const float* Ac = As[kt & 1];
        const float* Bc = Bs[kt & 1];

        #pragma unroll
        for (int kk = 0; kk < 2; kk++) {
            const int krow = kk * 8 + (lane & 3);
            unsigned afr[2][4];
            unsigned bfr[4][2];
            #pragma unroll
            for (int mt = 0; mt < 2; mt++) {
                int r = warp_m * 32 + mt * 16 + (lane >> 2);
                afr[mt][0] = __float_as_uint(Ac[(r    ) * 17 + krow    ]);
                afr[mt][1] = __float_as_uint(Ac[(r + 8) * 17 + krow    ]);
                afr[mt][2] = __float_as_uint(Ac[(r    ) * 17 + krow + 4]);
                afr[mt][3] = __float_as_uint(Ac[(r + 8) * 17 + krow + 4]);
            }
            #pragma unroll
            for (int nt = 0; nt < 4; nt++) {
                int n = warp_n * 32 + nt * 8 + (lane >> 2);
                bfr[nt][0] = __float_as_uint(Bc[n * 17 + krow    ]);
                bfr[nt][1] = __float_as_uint(Bc[n * 17 + krow + 4]);
            }
            #pragma unroll
            for (int mt = 0; mt < 2; mt++)
                #pragma unroll
                for (int nt = 0; nt < 4; nt++)
                    mma_tf32(acc[mt][nt], afr[mt], bfr[nt]);
        }

        if (kt + 1 < NKT) {
            sts_tile((kt + 1) & 1);
            __syncthreads();
        }
    }

    // epilogue ----------------------------------------------------------------
    // thread holds: rows {warp_m*32 + mt*16 + lane/4 + 8*half}, cols {hbase, hbase+1}
    // for all 4 gates (gate == nt by construction of the permutation).
    const int hbase = ctan * 16 + warp_n * 8 + 2 * (lane & 3);

    float bi0 = __ldg(bias + 0 * HH + hbase), bi1 = __ldg(bias + 0 * HH + hbase + 1);
    float bf0 = __ldg(bias + 1 * HH + hbase), bf1 = __ldg(bias + 1 * HH + hbase + 1);
    float bg0 = __ldg(bias + 2 * HH + hbase), bg1 = __ldg(bias + 2 * HH + hbase + 1);
    float bo0 = __ldg(bias + 3 * HH + hbase), bo1 = __ldg(bias + 3 * HH + hbase + 1);

    #pragma unroll
    for (int mt = 0; mt < 2; mt++) {
        #pragma unroll
        for (int half = 0; half < 2; half++) {
            int r = mtile * 128 + warp_m * 32 + mt * 16 + (lane >> 2) + half * 8;
            float hn[2], cn[2];
            #pragma unroll
            for (int j = 0; j < 2; j++) {
                int c2 = half * 2 + j;
                float gi = acc[mt][0][c2] + (j ? bi1 : bi0);
                float gf = acc[mt][1][c2] + (j ? bf1 : bf0);
                float gg = acc[mt][2][c2] + (j ? bg1 : bg0);
                float go = acc[mt][3][c2] + (j ? bo1 : bo0);
                float ii = sigf(gi);
                float ff = sigf(gf);
                float tg = tanhf(gg);
                float oo = sigf(go);
                long cidx = (long)r * HH + hbase + j;
                float cold = g_c[cidx];
                float cnew = ff * cold + ii * tg;
                float hnew = oo * tanhf(cnew);
                g_c[cidx] = cnew;
                out[((long)r * TT + t) * HH + hbase + j] = hnew;
                if (t == TT - 1) {
                    out[BTH + (long)r * HH + hbase + j]      = hnew;
                    out[BTH + BH + (long)r * HH + hbase + j] = cnew;
                }
                hn[j] = hnew;
                cn[j] = cnew;
            }
            (void)cn;
            // hidden carry with ODE state transform on cols 0,1 (both live here)
            float h0s = hn[0], h1s = hn[1];
            if (hbase == 0) {
                h0s = hn[0] + TAUc * (MHUc * hn[0] + hn[1] / MHUc);
                h1s = hn[1] + TAUc * (-MHUc * hn[0]);
            }
            hdst[(long)r * HH + hbase + 0] = h0s;
            hdst[(long)r * HH + hbase + 1] = h1s;
        }
    }
}

// ---------------------------------------------------------------------------
extern "C" void kernel_launch(void* const* d_in, const int* in_sizes, int n_in,
                              void* d_out, int out_size) {
    const float* x  = (const float*)d_in[0];   // rnn_input (B,T,I)
    const float* h0 = (const float*)d_in[1];   // (1,B,H)
    const float* c0 = (const float*)d_in[2];   // (1,B,H)
    const float* Wx = (const float*)d_in[3];   // (I,4H)
    const float* Wh = (const float*)d_in[4];   // (H,4H)
    const float* b  = (const float*)d_in[5];   // (4H,)
    float* out = (float*)d_out;

    // one-shot weight permutation + tf32 rounding (runs every replay; ~tens of us)
    {
        long total = (long)NG * KTOT;
        int blocks = (int)((total + 255) / 256);
        transform_W<<<blocks, 256>>>(Wx, Wh);
    }
    init_state<<<(BB * HH + 255) / 256, 256>>>(h0, c0);

    for (int t = 0; t < TT; t++) {
        lstm_step<<<dim3(64, 2), 256>>>(x, b, out, t, t & 1);
    }
}

// round 2
// speedup vs baseline: 2.2273x; 2.2273x over previous
#include <cuda_runtime.h>
#include <cuda_bf16.h>
#include <math.h>

// Problem constants
#define BB   256
#define TT   256
#define II   256
#define HH   1024
#define KTOT 1280           // I + H
#define NG   4096           // 4*H
#define TAUc 0.05f
#define MHUc 1.5f

#define BTH  ((long)BB * TT * HH)
#define BH   ((long)BB * HH)

// k-block = 8 k-values, m/n-block = 16 rows / 8 cols (mma m16n8k8 fragment tiles)
#define XKB  32             // x k-blocks (I/8)
#define HKB  128            // h k-blocks (H/8)
#define WKB  160            // total k-blocks (KTOT/8)
#define NB_TOT 512          // n-blocks (NG/8)
#define BK   32             // k per pipeline stage
#define NKT  40             // KTOT/BK
#define STAGES 4

// ---------------------------------------------------------------------------
// Persistent device scratch (static __device__ arrays: allocation-free)
// All stored PRE-ROUNDED to tf32 and PRE-PACKED in mma-fragment order.
//
// A-fragment pack (m16n8k8, 16x8 block): value j of lane l is
//   row' = (l>>2) + 8*(j&1),  k' = (l&3) + 4*(j>>1)       -> [lane][4] floats
// B-fragment pack (8x8 block): value j of lane l is
//   k' = (l&3) + 4*j,  n' = l>>2                          -> [lane][2] floats
// ---------------------------------------------------------------------------
__device__ float g_xp[(long)TT * 16 * XKB * 128];   // [t][mb16][kb][lane][4]  (67MB)
__device__ float g_hp[2][16 * HKB * 128];           // [mb16][kb][lane][4]
__device__ float g_Wp[(long)NB_TOT * WKB * 64];     // [nb][kb][lane][2]      (21MB)
__device__ float g_c[BB * HH];                      // cell state (linear)

__device__ __forceinline__ unsigned f2tf32(float v) {
    unsigned u;
    asm("cvt.rna.tf32.f32 %0, %1;" : "=r"(u) : "f"(v));
    return u;
}
__device__ __forceinline__ float sigf(float x) { return 1.0f / (1.0f + expf(-x)); }

// ---------------------------------------------------------------------------
// Packing kernels (run once per launch; iterate in PACKED order -> coalesced writes)
// Column permutation (as round 1): permuted col n -> gate=(n>>3)&3,
//   hcol = ((n>>6)<<4) | (((n>>5)&1)<<3) | (n&7)
// ---------------------------------------------------------------------------
__global__ void transform_x(const float* __restrict__ x) {
    long p = (long)blockIdx.x * blockDim.x + threadIdx.x;
    if (p >= (long)TT * 16 * XKB * 128) return;
    int j    = (int)(p & 3);
    int lane = (int)((p >> 2) & 31);
    long blk = p >> 7;
    int kb   = (int)(blk & 31);
    long tmb = blk >> 5;
    int mb   = (int)(tmb & 15);
    int t    = (int)(tmb >> 4);
    int rowp = (lane >> 2) + 8 * (j & 1);
    int kp   = (lane & 3) + 4 * (j >> 1);
    int b    = mb * 16 + rowp;
    int i    = kb * 8 + kp;
    float v = x[((long)b * TT + t) * II + i];
    g_xp[p] = __uint_as_float(f2tf32(v));
}

__global__ void transform_W(const float* __restrict__ Wx, const float* __restrict__ Wh) {
    long p = (long)blockIdx.x * blockDim.x + threadIdx.x;
    if (p >= (long)NB_TOT * WKB * 64) return;
    int j    = (int)(p & 1);
    int lane = (int)((p >> 1) & 31);
    long blk = p >> 6;
    int kb   = (int)(blk % WKB);
    int nb   = (int)(blk / WKB);
    int n    = nb * 8 + (lane >> 2);
    int k    = kb * 8 + (lane & 3) + 4 * j;
    int gate = (n >> 3) & 3;
    int hcol = ((n >> 6) << 4) | (((n >> 5) & 1) << 3) | (n & 7);
    int col  = gate * HH + hcol;
    float v = (k < II) ? Wx[(long)k * NG + col] : Wh[(long)(k - II) * NG + col];
    g_Wp[p] = __uint_as_float(f2tf32(v));
}

__global__ void init_state(const float* __restrict__ h0, const float* __restrict__ c0) {
    int p = blockIdx.x * blockDim.x + threadIdx.x;
    if (p >= BB * HH) return;
    int j    = p & 3;
    int lane = (p >> 2) & 31;
    int blk  = p >> 7;
    int kb   = blk & 127;
    int mb   = blk >> 7;
    int rowp = (lane >> 2) + 8 * (j & 1);
    int kp   = (lane & 3) + 4 * (j >> 1);
    int b    = mb * 16 + rowp;
    int hc   = kb * 8 + kp;
    g_hp[0][p] = __uint_as_float(f2tf32(h0[b * HH + hc]));
    g_c[p] = c0[p];
}

// ---------------------------------------------------------------------------
// cp.async helpers
// ---------------------------------------------------------------------------
__device__ __forceinline__ void cp16(unsigned saddr, const void* g) {
    asm volatile("cp.async.cg.shared.global [%0], [%1], 16;\n" :: "r"(saddr), "l"(g));
}
#define CP_COMMIT()   asm volatile("cp.async.commit_group;\n" ::: "memory")
#define CP_WAIT(N)    asm volatile("cp.async.wait_group %0;\n" :: "n"(N) : "memory")

__device__ __forceinline__ void mma_tf32(float* d, const unsigned* a, const unsigned* b) {
    asm volatile(
        "mma.sync.aligned.m16n8k8.row.col.f32.tf32.tf32.f32 "
        "{%0,%1,%2,%3}, {%4,%5,%6,%7}, {%8,%9}, {%0,%1,%2,%3};"
        : "+f"(d[0]), "+f"(d[1]), "+f"(d[2]), "+f"(d[3])
        : "r"(a[0]), "r"(a[1]), "r"(a[2]), "r"(a[3]), "r"(b[0]), "r"(b[1]));
}

// ---------------------------------------------------------------------------
// Per-step fused kernel.
// BM=128, BN=64, BK=32, 256 threads = 8 warps (4 m x 2 n), warp tile 32x32.
// Grid (64 N-tiles, 2 M-tiles) = 128 CTAs.
// Dynamic smem: A 4 stages x 1024 float4 + B 4 stages x 512 float4 = 96KB.
// ---------------------------------------------------------------------------
__global__ void __launch_bounds__(256, 1)
lstm_step(const float* __restrict__ bias,   // (4H,)
          float* __restrict__ out,          // outputs | hN | cN
          int t, int srcbuf)
{
    extern __shared__ float4 smem[];
    float4* sA4 = smem;               // [4][1024]
    float4* sB4 = smem + STAGES * 1024;

    const float* __restrict__ hsrc = g_hp[srcbuf];
    float*       __restrict__ hdst = g_hp[srcbuf ^ 1];

    const int tid    = threadIdx.x;
    const int lane   = tid & 31;
    const int warp   = tid >> 5;
    const int warp_m = warp >> 1;        // 0..3
    const int warp_n = warp & 1;         // 0..1
    const int ctan   = blockIdx.x;       // 0..63
    const int mtile  = blockIdx.y;       // 0..1

    const unsigned sA_base = (unsigned)__cvta_generic_to_shared(sA4);
    const unsigned sB_base = (unsigned)__cvta_generic_to_shared(sB4);

    float acc[2][4][4];
    #pragma unroll
    for (int a = 0; a < 2; a++)
        #pragma unroll
        for (int q = 0; q < 4; q++)
            #pragma unroll
            for (int c = 0; c < 4; c++) acc[a][q][c] = 0.0f;

    // ---- stage issue -------------------------------------------------------
    auto issue = [&](int kt) {
        int s = kt & (STAGES - 1);
        // A: 1024 float4 per stage, 4 per thread
        #pragma unroll
        for (int r = 0; r < 4; r++) {
            int idx = tid + 256 * r;
            int mb  = idx >> 7;          // 0..7
            int kb  = (idx >> 5) & 3;
            int li  = idx & 31;
            const float* src;
            if (t >= 0 && kt < 8) {
                src = g_xp + (((((long)t * 16 + (mtile * 8 + mb)) * XKB) + (kt * 4 + kb)) * 32 + li) * 4;
            } else {
                src = hsrc + ((((mtile * 8 + mb) * HKB) + ((kt - 8) * 4 + kb)) * 32 + li) * 4;
            }
            cp16(sA_base + (unsigned)(s * 1024 + idx) * 16, src);
        }
        // B: 512 float4 per stage, 2 per thread
        #pragma unroll
        for (int r = 0; r < 2; r++) {
            int idx = tid + 256 * r;
            int nb  = idx >> 6;          // 0..7
            int kb  = (idx >> 4) & 3;
            int li  = idx & 15;
            const float* src = g_Wp + ((((long)(ctan * 8 + nb) * WKB) + (kt * 4 + kb)) * 16 + li) * 4;
            cp16(sB_base + (unsigned)(s * 512 + idx) * 16, src);
        }
    };

    // prologue: fill 3 stages
    issue(0); CP_COMMIT();
    issue(1); CP_COMMIT();
    issue(2); CP_COMMIT();

    // ---- main K loop -------------------------------------------------------
    for (int kt = 0; kt < NKT; kt++) {
        CP_WAIT(2);
        __syncthreads();

        int s = kt & (STAGES - 1);
        const float4* A4 = sA4 + s * 1024;
        const float2* B2 = (const float2*)(sB4 + s * 512);

        #pragma unroll
        for (int kk = 0; kk < 4; kk++) {
            float4 af[2];
            #pragma unroll
            for (int mt = 0; mt < 2; mt++)
                af[mt] = A4[((warp_m * 2 + mt) * 4 + kk) * 32 + lane];
            float2 bf[4];
            #pragma unroll
            for (int nt = 0; nt < 4; nt++)
                bf[nt] = B2[((warp_n * 4 + nt) * 4 + kk) * 32 + lane];
            #pragma unroll
            for (int mt = 0; mt < 2; mt++)
                #pragma unroll
                for (int nt = 0; nt < 4; nt++)
                    mma_tf32(acc[mt][nt], (const unsigned*)&af[mt], (const unsigned*)&bf[nt]);
        }

        __syncthreads();
        if (kt + 3 < NKT) issue(kt + 3);
        CP_COMMIT();
    }

    // ---- epilogue ----------------------------------------------------------
    // warp's 32 permuted cols = {4 gates (nt)} x {8 h-cols}; thread holds cols
    // hbase, hbase+1 for all 4 gates at rows (mt, half).
    const int hbase = ctan * 16 + warp_n * 8 + 2 * (lane & 3);

    float bi0 = __ldg(bias + 0 * HH + hbase), bi1 = __ldg(bias + 0 * HH + hbase + 1);
    float bf0 = __ldg(bias + 1 * HH + hbase), bf1 = __ldg(bias + 1 * HH + hbase + 1);
    float bg0 = __ldg(bias + 2 * HH + hbase), bg1 = __ldg(bias + 2 * HH + hbase + 1);
    float bo0 = __ldg(bias + 3 * HH + hbase), bo1 = __ldg(bias + 3 * HH + hbase + 1);

    const int kb_pack = ctan * 2 + warp_n;   // h k-block this thread's 2 cols live in

    #pragma unroll
    for (int mt = 0; mt < 2; mt++) {
        #pragma unroll
        for (int half = 0; half < 2; half++) {
            int r = mtile * 128 + warp_m * 32 + mt * 16 + (lane >> 2) + half * 8;
            float hn[2];
            #pragma unroll
            for (int j = 0; j < 2; j++) {
                int c2 = half * 2 + j;
                float gi = acc[mt][0][c2] + (j ? bi1 : bi0);
                float gf = acc[mt][1][c2] + (j ? bf1 : bf0);
                float gg = acc[mt][2][c2] + (j ? bg1 : bg0);
                float go = acc[mt][3][c2] + (j ? bo1 : bo0);
                float ii = sigf(gi);
                float ff = sigf(gf);
                float tg = tanhf(gg);
                float oo = sigf(go);
                long cidx = (long)r * HH + hbase + j;
                float cold = g_c[cidx];
                float cnew = ff * cold + ii * tg;
                float hnew = oo * tanhf(cnew);
                g_c[cidx] = cnew;
                out[((long)r * TT + t) * HH + hbase + j] = hnew;
                if (t == TT - 1) {
                    out[BTH + (long)r * HH + hbase + j]      = hnew;
                    out[BTH + BH + (long)r * HH + hbase + j] = cnew;
                }
                hn[j] = hnew;
            }
            // ODE transform on h-cols 0,1 (both live in this thread when hbase==0)
            float h0s = hn[0], h1s = hn[1];
            if (hbase == 0) {
                h0s = hn[0] + TAUc * (MHUc * hn[0] + hn[1] / MHUc);
                h1s = hn[1] + TAUc * (-MHUc * hn[0]);
            }
            // store carry into PACKED layout, tf32-rounded
            int mb   = r >> 4;
            int rowp = r & 15;
            #pragma unroll
            for (int j = 0; j < 2; j++) {
                int kp    = 2 * (lane & 3) + j;            // hc & 7
                int lanep = ((rowp & 7) << 2) | (kp & 3);
                int jj    = (rowp >> 3) | (((kp >> 2) & 1) << 1);
                float v = j ? h1s : h0s;
                hdst[((mb * HKB + kb_pack) * 32 + lanep) * 4 + jj] =
                    __uint_as_float(f2tf32(v));
            }
        }
    }
}

// ---------------------------------------------------------------------------
extern "C" void kernel_launch(void* const* d_in, const int* in_sizes, int n_in,
                              void* d_out, int out_size) {
    const float* x  = (const float*)d_in[0];   // rnn_input (B,T,I)
    const float* h0 = (const float*)d_in[1];   // (1,B,H)
    const float* c0 = (const float*)d_in[2];   // (1,B,H)
    const float* Wx = (const float*)d_in[3];   // (I,4H)
    const float* Wh = (const float*)d_in[4];   // (H,4H)
    const float* b  = (const float*)d_in[5];   // (4H,)
    float* out = (float*)d_out;

    cudaFuncSetAttribute(lstm_step, cudaFuncAttributeMaxDynamicSharedMemorySize,
                         STAGES * (1024 + 512) * 16);

    {
        long total = (long)TT * 16 * XKB * 128;
        transform_x<<<(int)((total + 255) / 256), 256>>>(x);
    }
    {
        long total = (long)NB_TOT * WKB * 64;
        transform_W<<<(int)((total + 255) / 256), 256>>>(Wx, Wh);
    }
    init_state<<<(BB * HH + 255) / 256, 256>>>(h0, c0);

    for (int t = 0; t < TT; t++) {
        lstm_step<<<dim3(64, 2), 256, STAGES * (1024 + 512) * 16>>>(b, out, t, t & 1);
    }
}

// round 3
// speedup vs baseline: 2.4031x; 1.0789x over previous
#include <cuda_runtime.h>
#include <cuda_bf16.h>
#include <math.h>

// Problem constants
#define BB   256
#define TT   256
#define II   256
#define HH   1024
#define KTOT 1280           // I + H
#define NG   4096           // 4*H
#define TAUc 0.05f
#define MHUc 1.5f

#define BTH  ((long)BB * TT * HH)
#define BH   ((long)BB * HH)

// k-block = 8 k-values, m-block = 16 rows, n-block = 8 cols (m16n8k8 fragments)
#define XKB  32             // x k-blocks (I/8)
#define HKB  128            // h k-blocks (H/8)
#define WKB  160            // total k-blocks (KTOT/8)
#define NB_TOT 512          // n-blocks (NG/8)
#define BK   32             // k per pipeline stage
#define NKT  40             // KTOT/BK
#define STAGES 4

// ---------------------------------------------------------------------------
// Persistent device scratch, pre-rounded to tf32, packed in mma-fragment order.
// A-frag (16x8): value j of lane l -> row'=(l>>2)+8*(j&1), k'=(l&3)+4*(j>>1)
// B-frag (8x8):  value j of lane l -> k'=(l&3)+4*j, n'=l>>2
// ---------------------------------------------------------------------------
__device__ float g_xp[(long)TT * 16 * XKB * 128];   // [t][mb16][kb][lane][4]
__device__ float g_hp[2][16 * HKB * 128];           // [mb16][kb][lane][4]
__device__ float g_Wp[(long)NB_TOT * WKB * 64];     // [nb][kb][lane][2]
__device__ float g_c[BB * HH];                      // cell state (linear)

__device__ __forceinline__ unsigned f2tf32(float v) {
    unsigned u;
    asm("cvt.rna.tf32.f32 %0, %1;" : "=r"(u) : "f"(v));
    return u;
}
__device__ __forceinline__ float sigf(float x) { return 1.0f / (1.0f + expf(-x)); }

// ---------------------------------------------------------------------------
// Packing kernels. Column permutation: permuted col n -> gate=(n>>3)&3,
//   hcol = ((n>>6)<<4) | (((n>>5)&1)<<3) | (n&7)
// ---------------------------------------------------------------------------
__global__ void transform_x(const float* __restrict__ x) {
    long p = (long)blockIdx.x * blockDim.x + threadIdx.x;
    if (p >= (long)TT * 16 * XKB * 128) return;
    int j    = (int)(p & 3);
    int lane = (int)((p >> 2) & 31);
    long blk = p >> 7;
    int kb   = (int)(blk & 31);
    long tmb = blk >> 5;
    int mb   = (int)(tmb & 15);
    int t    = (int)(tmb >> 4);
    int rowp = (lane >> 2) + 8 * (j & 1);
    int kp   = (lane & 3) + 4 * (j >> 1);
    int b    = mb * 16 + rowp;
    int i    = kb * 8 + kp;
    float v = x[((long)b * TT + t) * II + i];
    g_xp[p] = __uint_as_float(f2tf32(v));
}

__global__ void transform_W(const float* __restrict__ Wx, const float* __restrict__ Wh) {
    long p = (long)blockIdx.x * blockDim.x + threadIdx.x;
    if (p >= (long)NB_TOT * WKB * 64) return;
    int j    = (int)(p & 1);
    int lane = (int)((p >> 1) & 31);
    long blk = p >> 6;
    int kb   = (int)(blk % WKB);
    int nb   = (int)(blk / WKB);
    int n    = nb * 8 + (lane >> 2);
    int k    = kb * 8 + (lane & 3) + 4 * j;
    int gate = (n >> 3) & 3;
    int hcol = ((n >> 6) << 4) | (((n >> 5) & 1) << 3) | (n & 7);
    int col  = gate * HH + hcol;
    float v = (k < II) ? Wx[(long)k * NG + col] : Wh[(long)(k - II) * NG + col];
    g_Wp[p] = __uint_as_float(f2tf32(v));
}

__global__ void init_state(const float* __restrict__ h0, const float* __restrict__ c0) {
    int p = blockIdx.x * blockDim.x + threadIdx.x;
    if (p >= BB * HH) return;
    int j    = p & 3;
    int lane = (p >> 2) & 31;
    int blk  = p >> 7;
    int kb   = blk & 127;
    int mb   = blk >> 7;
    int rowp = (lane >> 2) + 8 * (j & 1);
    int kp   = (lane & 3) + 4 * (j >> 1);
    int b    = mb * 16 + rowp;
    int hc   = kb * 8 + kp;
    g_hp[0][p] = __uint_as_float(f2tf32(h0[b * HH + hc]));
    g_c[p] = c0[p];
}

// ---------------------------------------------------------------------------
__device__ __forceinline__ void cp16(unsigned saddr, const void* g) {
    asm volatile("cp.async.cg.shared.global [%0], [%1], 16;\n" :: "r"(saddr), "l"(g));
}
#define CP_COMMIT()   asm volatile("cp.async.commit_group;\n" ::: "memory")
#define CP_WAIT(N)    asm volatile("cp.async.wait_group %0;\n" :: "n"(N) : "memory")

__device__ __forceinline__ void mma_tf32(float* d, const unsigned* a, const unsigned* b) {
    asm volatile(
        "mma.sync.aligned.m16n8k8.row.col.f32.tf32.tf32.f32 "
        "{%0,%1,%2,%3}, {%4,%5,%6,%7}, {%8,%9}, {%0,%1,%2,%3};"
        : "+f"(d[0]), "+f"(d[1]), "+f"(d[2]), "+f"(d[3])
        : "r"(a[0]), "r"(a[1]), "r"(a[2]), "r"(a[3]), "r"(b[0]), "r"(b[1]));
}

// ---------------------------------------------------------------------------
// Per-step fused kernel.
// BM=128, BN=64, BK=32, 512 threads = 16 warps (8 m x 2 n), warp tile 16x32.
// Grid (64 N-tiles, 2 M-tiles) = 128 CTAs, 1/SM, 16 warps/SM.
// Dynamic smem: 4 stages x (1024 A + 512 B) float4 = 96KB.
// ---------------------------------------------------------------------------
__global__ void __launch_bounds__(512, 1)
lstm_step(const float* __restrict__ bias,   // (4H,)
          float* __restrict__ out,          // outputs | hN | cN
          int t, int srcbuf)
{
    extern __shared__ float4 smem[];
    float4* sA4 = smem;               // [4][1024]
    float4* sB4 = smem + STAGES * 1024;

    const float* __restrict__ hsrc = g_hp[srcbuf];
    float*       __restrict__ hdst = g_hp[srcbuf ^ 1];

    const int tid    = threadIdx.x;
    const int lane   = tid & 31;
    const int warp   = tid >> 5;
    const int warp_m = warp >> 1;        // 0..7 (16 rows each)
    const int warp_n = warp & 1;         // 0..1 (32 cols each)
    const int ctan   = blockIdx.x;       // 0..63
    const int mtile  = blockIdx.y;       // 0..1

    const unsigned sA_base = (unsigned)__cvta_generic_to_shared(sA4);
    const unsigned sB_base = (unsigned)__cvta_generic_to_shared(sB4);

    // columns this thread owns (same for all row groups): hbase, hbase+1
    const int hbase = ctan * 16 + warp_n * 8 + 2 * (lane & 3);

    // init accumulators with bias (acc[nt=gate][c], col = hbase + (c&1))
    float acc[4][4];
    {
        #pragma unroll
        for (int g = 0; g < 4; g++) {
            float b0 = __ldg(bias + g * HH + hbase);
            float b1 = __ldg(bias + g * HH + hbase + 1);
            acc[g][0] = b0; acc[g][1] = b1; acc[g][2] = b0; acc[g][3] = b1;
        }
    }

    // ---- stage issue: A 1024 float4 (2/thread), B 512 float4 (1/thread) ----
    auto issue = [&](int kt) {
        int s = kt & (STAGES - 1);
        #pragma unroll
        for (int r = 0; r < 2; r++) {
            int idx = tid + 512 * r;
            int mb  = idx >> 7;          // 0..7
            int kb  = (idx >> 5) & 3;
            int li  = idx & 31;
            const float* src;
            if (kt < 8) {
                src = g_xp + (((((long)t * 16 + (mtile * 8 + mb)) * XKB) + (kt * 4 + kb)) * 32 + li) * 4;
            } else {
                src = hsrc + ((((mtile * 8 + mb) * HKB) + ((kt - 8) * 4 + kb)) * 32 + li) * 4;
            }
            cp16(sA_base + (unsigned)(s * 1024 + idx) * 16, src);
        }
        {
            int idx = tid;
            int nb  = idx >> 6;          // 0..7
            int kb  = (idx >> 4) & 3;
            int li  = idx & 15;
            const float* src = g_Wp + ((((long)(ctan * 8 + nb) * WKB) + (kt * 4 + kb)) * 16 + li) * 4;
            cp16(sB_base + (unsigned)(s * 512 + idx) * 16, src);
        }
    };

    // prologue: fill 3 stages
    issue(0); CP_COMMIT();
    issue(1); CP_COMMIT();
    issue(2); CP_COMMIT();

    // ---- main K loop (ONE barrier per iteration) ---------------------------
    for (int kt = 0; kt < NKT; kt++) {
        CP_WAIT(2);
        __syncthreads();

        int s = kt & (STAGES - 1);
        const float4* A4 = sA4 + s * 1024;
        const float2* B2 = (const float2*)(sB4 + s * 512);

        #pragma unroll
        for (int kk = 0; kk < 4; kk++) {
            float4 af = A4[(warp_m * 4 + kk) * 32 + lane];
            float2 bf[4];
            #pragma unroll
            for (int nt = 0; nt < 4; nt++)
                bf[nt] = B2[((warp_n * 4 + nt) * 4 + kk) * 32 + lane];
            #pragma unroll
            for (int nt = 0; nt < 4; nt++)
                mma_tf32(acc[nt], (const unsigned*)&af, (const unsigned*)&bf[nt]);
        }

        // stage (kt+3)&3 == (kt-1)&3: its readers all passed the barrier above
        if (kt + 3 < NKT) issue(kt + 3);
        CP_COMMIT();
    }

    // ---- epilogue ----------------------------------------------------------
    const int kb_pack = ctan * 2 + warp_n;   // h k-block holding this thread's cols

    #pragma unroll
    for (int half = 0; half < 2; half++) {
        int r = mtile * 128 + warp_m * 16 + (lane >> 2) + half * 8;
        long cidx = (long)r * HH + hbase;
        float2 cold = *(const float2*)(g_c + cidx);
        float hn[2], cn[2];
        #pragma unroll
        for (int j = 0; j < 2; j++) {
            int c2 = half * 2 + j;
            float ii = sigf(acc[0][c2]);
            float ff = sigf(acc[1][c2]);
            float tg = tanhf(acc[2][c2]);
            float oo = sigf(acc[3][c2]);
            float cnew = ff * (j ? cold.y : cold.x) + ii * tg;
            cn[j] = cnew;
            hn[j] = oo * tanhf(cnew);
        }
        *(float2*)(g_c + cidx) = make_float2(cn[0], cn[1]);
        *(float2*)(out + ((long)r * TT + t) * HH + hbase) = make_float2(hn[0], hn[1]);
        if (t == TT - 1) {
            *(float2*)(out + BTH + (long)r * HH + hbase)      = make_float2(hn[0], hn[1]);
            *(float2*)(out + BTH + BH + (long)r * HH + hbase) = make_float2(cn[0], cn[1]);
        }
        // ODE transform on h-cols 0,1 (both live here when hbase==0)
        float h0s = hn[0], h1s = hn[1];
        if (hbase == 0) {
            h0s = hn[0] + TAUc * (MHUc * hn[0] + hn[1] / MHUc);
            h1s = hn[1] + TAUc * (-MHUc * hn[0]);
        }
        // store carry into packed layout, tf32-rounded
        int mb   = r >> 4;
        int rowp = r & 15;
        #pragma unroll
        for (int j = 0; j < 2; j++) {
            int kp    = 2 * (lane & 3) + j;            // hc & 7
            int lanep = ((rowp & 7) << 2) | (kp & 3);
            int jj    = (rowp >> 3) | (((kp >> 2) & 1) << 1);
            float v = j ? h1s : h0s;
            hdst[((mb * HKB + kb_pack) * 32 + lanep) * 4 + jj] =
                __uint_as_float(f2tf32(v));
        }
    }
}

// ---------------------------------------------------------------------------
extern "C" void kernel_launch(void* const* d_in, const int* in_sizes, int n_in,
                              void* d_out, int out_size) {
    const float* x  = (const float*)d_in[0];   // rnn_input (B,T,I)
    const float* h0 = (const float*)d_in[1];   // (1,B,H)
    const float* c0 = (const float*)d_in[2];   // (1,B,H)
    const float* Wx = (const float*)d_in[3];   // (I,4H)
    const float* Wh = (const float*)d_in[4];   // (H,4H)
    const float* b  = (const float*)d_in[5];   // (4H,)
    float* out = (float*)d_out;

    cudaFuncSetAttribute(lstm_step, cudaFuncAttributeMaxDynamicSharedMemorySize,
                         STAGES * (1024 + 512) * 16);

    {
        long total = (long)TT * 16 * XKB * 128;
        transform_x<<<(int)((total + 255) / 256), 256>>>(x);
    }
    {
        long total = (long)NB_TOT * WKB * 64;
        transform_W<<<(int)((total + 255) / 256), 256>>>(Wx, Wh);
    }
    init_state<<<(BB * HH + 255) / 256, 256>>>(h0, c0);

    for (int t = 0; t < TT; t++) {
        lstm_step<<<dim3(64, 2), 512, STAGES * (1024 + 512) * 16>>>(b, out, t, t & 1);
    }
}

// round 5
// speedup vs baseline: 4.3618x; 1.8151x over previous
#include <cuda_runtime.h>
#include <cuda_fp16.h>
#include <math.h>
#include <stdint.h>

// Problem constants
#define BB   256
#define TT   256
#define II   256
#define HH   1024
#define KTOT 1280
#define NG   4096
#define TAUc 0.05f
#define MHUc 1.5f
#define BTH  ((long)BB * TT * HH)
#define BH   ((long)BB * HH)

// Tiling: BM=128, BN=64, BK=32 (2 x k16). Grid (64 ctan, 2 mtile) = 128 CTAs.
// 512 threads = 16 warps, 8 m-warps x 2 n-warps, warp tile 16x32.
#define BK     32
#define NKT    40          // KTOT/BK
#define XKT    8           // x stages (II/BK)
#define STAGES 4
#define A_IMG  2048        // uint32 per A stage image (128 rows x 32 k fp16)
#define B_IMG  1024        // uint32 per B stage image (64 n x 32 k fp16)

// ---------------------------------------------------------------------------
// Persistent scratch. Operand images are stored EXACTLY as the smem stage
// should look: mma-fragment register images (fp16), so per-step copies are
// pure linear cp.async.
//
// A image: [mb(8)][kb16(2)][lane(32)][reg(4)] uint32; m16n8k16 A-frag mapping:
//   reg j, half h: row' = (lane>>2) + 8*(j&1), k' = (lane&3)*2 + 8*(j>>1) + h
// B image: [nbp(4)][kb16(2)][lane(32)][j(4)] uint32; j = (nb&1)*? ->
//   nb = nbp*2 + (j>>1), reg r = j&1: k = r*8 + (lane&3)*2 + h, n = nb*8 + (lane>>2)
// ---------------------------------------------------------------------------
__device__ uint32_t g_xp[(long)TT * 2 * XKT * A_IMG];   // 32MB
__device__ uint32_t g_hp[2][2 * 32 * A_IMG];            // h carry images
__device__ uint32_t g_Wp[(long)64 * NKT * B_IMG];       // 10MB
__device__ float    g_c[BB * HH];                       // cell state (linear)

__device__ __forceinline__ float sigf(float x) { return 1.0f / (1.0f + expf(-x)); }

// ---------------------------------------------------------------------------
// Column permutation (identical to round 3): permuted col n ->
//   gate = (n>>3)&3, hcol = ((n>>6)<<4) | (((n>>5)&1)<<3) | (n&7)
// Warp's 32 cols = {4 gates} x {8 h-cols}; epilogue thread owns 2 h-cols x 4 gates.
// ---------------------------------------------------------------------------
__global__ void transform_x(const float* __restrict__ x) {
    uint32_t p = blockIdx.x * blockDim.x + threadIdx.x;   // 8,388,608 total
    int j    = p & 3;
    int lane = (p >> 2) & 31;
    int kb   = (p >> 7) & 1;
    int mb   = (p >> 8) & 7;
    int kt   = (p >> 11) & 7;
    int mt   = (p >> 14) & 1;
    int t    = p >> 15;
    int rowp = (lane >> 2) + 8 * (j & 1);
    int kp   = (lane & 3) * 2 + 8 * (j >> 1);
    int b    = mt * 128 + mb * 16 + rowp;
    int i    = kt * 32 + kb * 16 + kp;
    const float* src = x + ((long)b * TT + t) * II + i;
    __half2 v = __floats2half2_rn(src[0], src[1]);
    g_xp[p] = *(uint32_t*)&v;
}

__global__ void transform_W(const float* __restrict__ Wx, const float* __restrict__ Wh) {
    uint32_t p = blockIdx.x * blockDim.x + threadIdx.x;
    if (p >= (uint32_t)64 * NKT * B_IMG) return;
    int j    = p & 3;
    int lane = (p >> 2) & 31;
    int kb   = (p >> 7) & 1;
    int nbp  = (p >> 8) & 3;
    int kt   = (int)((p >> 10) % NKT);
    int ctan = (int)((p >> 10) / NKT);
    int nb   = nbp * 2 + (j >> 1);
    int r    = j & 1;
    int n    = ctan * 64 + nb * 8 + (lane >> 2);
    int gate = (n >> 3) & 3;
    int hcol = ((n >> 6) << 4) | (((n >> 5) & 1) << 3) | (n & 7);
    int col  = gate * HH + hcol;
    int kg   = kt * 32 + kb * 16 + r * 8 + (lane & 3) * 2;
    float v0 = (kg < II)     ? Wx[(long)kg * NG + col]       : Wh[(long)(kg - II) * NG + col];
    float v1 = (kg + 1 < II) ? Wx[(long)(kg + 1) * NG + col] : Wh[(long)(kg + 1 - II) * NG + col];
    __half2 v = __floats2half2_rn(v0, v1);
    g_Wp[p] = *(uint32_t*)&v;
}

__global__ void init_state(const float* __restrict__ h0, const float* __restrict__ c0) {
    uint32_t p = blockIdx.x * blockDim.x + threadIdx.x;
    if (p >= 262144) return;
    if (p < 131072) {   // h0 -> packed A images
        int j    = p & 3;
        int lane = (p >> 2) & 31;
        int kb   = (p >> 7) & 1;
        int mb   = (p >> 8) & 7;
        int hkt  = (p >> 11) & 31;
        int mt   = (p >> 16) & 1;
        int rowp = (lane >> 2) + 8 * (j & 1);
        int kp   = (lane & 3) * 2 + 8 * (j >> 1);
        int b    = mt * 128 + mb * 16 + rowp;
        int hc   = hkt * 32 + kb * 16 + kp;
        __half2 v = __floats2half2_rn(h0[b * HH + hc], h0[b * HH + hc + 1]);
        g_hp[0][p] = *(uint32_t*)&v;
    }
    g_c[p] = c0[p];
}

// ---------------------------------------------------------------------------
__device__ __forceinline__ void cp16(uint32_t saddr, const void* g) {
    asm volatile("cp.async.cg.shared.global [%0], [%1], 16;\n" :: "r"(saddr), "l"(g));
}
#define CP_COMMIT() asm volatile("cp.async.commit_group;\n" ::: "memory")
#define CP_WAIT(N)  asm volatile("cp.async.wait_group %0;\n" :: "n"(N) : "memory")

__device__ __forceinline__ void mma16816(float* d, const uint4& a, uint32_t b0, uint32_t b1) {
    asm volatile(
        "mma.sync.aligned.m16n8k16.row.col.f32.f16.f16.f32 "
        "{%0,%1,%2,%3}, {%4,%5,%6,%7}, {%8,%9}, {%0,%1,%2,%3};"
        : "+f"(d[0]), "+f"(d[1]), "+f"(d[2]), "+f"(d[3])
        : "r"(a.x), "r"(a.y), "r"(a.z), "r"(a.w), "r"(b0), "r"(b1));
}

// ---------------------------------------------------------------------------
// Per-step fused kernel.
// ---------------------------------------------------------------------------
__global__ void __launch_bounds__(512, 1)
lstm_step(const float* __restrict__ bias,   // (4H,)
          float* __restrict__ out,          // outputs | hN | cN
          int t, int srcbuf)
{
    __shared__ uint4 sA[STAGES][512];   // 32KB: A stage = 2048 uint32
    __shared__ uint4 sB[STAGES][256];   // 16KB: B stage = 1024 uint32

    const uint32_t* __restrict__ hsrc = g_hp[srcbuf];
    uint32_t*       __restrict__ hdst = g_hp[srcbuf ^ 1];

    const int tid    = threadIdx.x;
    const int lane   = tid & 31;
    const int warp   = tid >> 5;
    const int warp_m = warp >> 1;        // 0..7
    const int warp_n = warp & 1;         // 0..1
    const int ctan   = blockIdx.x;       // 0..63
    const int mt     = blockIdx.y;       // 0..1

    // columns this thread owns: hbase, hbase+1 (for all 4 gates)
    const int hbase = ctan * 16 + warp_n * 8 + 2 * (lane & 3);

    // accumulators init with bias: acc[gate][c], col = hbase + (c&1), row group (c>>1)
    float acc[4][4];
    #pragma unroll
    for (int g = 0; g < 4; g++) {
        float b0 = __ldg(bias + g * HH + hbase);
        float b1 = __ldg(bias + g * HH + hbase + 1);
        acc[g][0] = b0; acc[g][1] = b1; acc[g][2] = b0; acc[g][3] = b1;
    }

    // stage loader: pure linear copy of pre-packed images
    auto issue = [&](int kt) {
        int s = kt & (STAGES - 1);
        const uint32_t* asrc = (kt < XKT)
            ? g_xp + ((long)(t * 2 + mt) * XKT + kt) * A_IMG
            : hsrc + (long)(mt * 32 + (kt - XKT)) * A_IMG;
        cp16((uint32_t)__cvta_generic_to_shared(&sA[s][tid]), asrc + tid * 4);
        if (tid < 256) {
            const uint32_t* bsrc = g_Wp + ((long)ctan * NKT + kt) * B_IMG;
            cp16((uint32_t)__cvta_generic_to_shared(&sB[s][tid]), bsrc + tid * 4);
        }
    };

    issue(0); CP_COMMIT();
    issue(1); CP_COMMIT();
    issue(2); CP_COMMIT();

    for (int kt = 0; kt < NKT; kt++) {
        CP_WAIT(2);
        __syncthreads();

        int s = kt & (STAGES - 1);
        #pragma unroll
        for (int kk = 0; kk < 2; kk++) {          // two k16 chunks per stage
            uint4 a  = sA[s][(warp_m * 2 + kk) * 32 + lane];
            uint4 b0 = sB[s][((warp_n * 2 + 0) * 2 + kk) * 32 + lane];
            uint4 b1 = sB[s][((warp_n * 2 + 1) * 2 + kk) * 32 + lane];
            mma16816(acc[0], a, b0.x, b0.y);
            mma16816(acc[1], a, b0.z, b0.w);
            mma16816(acc[2], a, b1.x, b1.y);
            mma16816(acc[3], a, b1.z, b1.w);
        }

        if (kt + 3 < NKT) issue(kt + 3);   // stage (kt-1)&3: readers passed barrier above
        CP_COMMIT();
    }

    // ---- epilogue ----------------------------------------------------------
    #pragma unroll
    for (int half = 0; half < 2; half++) {
        int m_loc = warp_m * 16 + (lane >> 2) + half * 8;   // row within mtile
        int r = mt * 128 + m_loc;
        long cidx = (long)r * HH + hbase;
        float2 cold = *(const float2*)(g_c + cidx);
        float hn[2], cn[2];
        #pragma unroll
        for (int j = 0; j < 2; j++) {
            int c2 = half * 2 + j;
            float ii = sigf(acc[0][c2]);
            float ff = sigf(acc[1][c2]);
            float tg = tanhf(acc[2][c2]);
            float oo = sigf(acc[3][c2]);
            float cnew = ff * (j ? cold.y : cold.x) + ii * tg;
            cn[j] = cnew;
            hn[j] = oo * tanhf(cnew);
        }
        *(float2*)(g_c + cidx) = make_float2(cn[0], cn[1]);
        *(float2*)(out + ((long)r * TT + t) * HH + hbase) = make_float2(hn[0], hn[1]);
        if (t == TT - 1) {
            *(float2*)(out + BTH + (long)r * HH + hbase)      = make_float2(hn[0], hn[1]);
            *(float2*)(out + BTH + BH + (long)r * HH + hbase) = make_float2(cn[0], cn[1]);
        }
        // ODE transform on h-cols 0,1 (this thread owns both when hbase==0)
        float h0s = hn[0], h1s = hn[1];
        if (hbase == 0) {
            h0s = hn[0] + TAUc * (MHUc * hn[0] + hn[1] / MHUc);
            h1s = hn[1] - TAUc * (MHUc * hn[0]);
        }
        // carry store: one half2 into next step's packed A image
        int mb   = m_loc >> 4;
        int rowp = m_loc & 15;
        int hkt  = hbase >> 5;
        int kb   = (hbase >> 4) & 1;
        int jj   = ((rowp >> 3) & 1) | ((((hbase & 15) >= 8) ? 1 : 0) << 1);
        int lanep = ((rowp & 7) << 2) | ((hbase & 7) >> 1);
        __half2 hv = __floats2half2_rn(h0s, h1s);
        hdst[(long)(mt * 32 + hkt) * A_IMG + ((mb * 2 + kb) * 32 + lanep) * 4 + jj] =
            *(uint32_t*)&hv;
    }
}

// ---------------------------------------------------------------------------
extern "C" void kernel_launch(void* const* d_in, const int* in_sizes, int n_in,
                              void* d_out, int out_size) {
    const float* x  = (const float*)d_in[0];   // rnn_input (B,T,I)
    const float* h0 = (const float*)d_in[1];   // (1,B,H)
    const float* c0 = (const float*)d_in[2];   // (1,B,H)
    const float* Wx = (const float*)d_in[3];   // (I,4H)
    const float* Wh = (const float*)d_in[4];   // (H,4H)
    const float* b  = (const float*)d_in[5];   // (4H,)
    float* out = (float*)d_out;

    transform_x<<<32768, 256>>>(x);
    {
        long total = (long)64 * NKT * B_IMG;
        transform_W<<<(int)((total + 255) / 256), 256>>>(Wx, Wh);
    }
    init_state<<<1024, 256>>>(h0, c0);

    for (int t = 0; t < TT; t++) {
        lstm_step<<<dim3(64, 2), 512>>>(b, out, t, t & 1);
    }
}

// round 6
// speedup vs baseline: 4.7627x; 1.0919x over previous
#include <cuda_runtime.h>
#include <cuda_fp16.h>
#include <math.h>
#include <stdint.h>

// Problem constants
#define BB   256
#define TT   256
#define II   256
#define HH   1024
#define KTOT 1280
#define NG   4096
#define TAUc 0.05f
#define MHUc 1.5f
#define BTH  ((long)BB * TT * HH)
#define BH   ((long)BB * HH)

// Tiling: BM=128, BN=64. Stage = BK 64 (4 x k16). Grid (64 ctan, 2 mtile) = 128 CTAs.
// 512 threads = 16 warps, 8 m-warps x 2 n-warps, warp tile 16x32.
#define NKT    40          // k16x2 images (KTOT/32)
#define XKT    8           // x images per (t,mt)
#define NST    20          // stages per step (KTOT/64)
#define XST    4           // x stages
#define STAGES 4
#define A_IMG  2048        // uint32 per 32-k A image (128 rows x 32 k fp16)
#define B_IMG  1024        // uint32 per 32-k B image (64 n x 32 k fp16)
// stage sizes (uint4): A 1024, B 512
#define DSMEM  (STAGES * (4096 + 2048) * 4)

// ---------------------------------------------------------------------------
// Persistent scratch: operand images stored exactly as smem stages should look
// (mma-fragment register images, fp16) -> per-step copies are pure linear.
//
// A image: [mb(8)][kb16(2)][lane(32)][reg(4)] uint32; m16n8k16 A-frag mapping:
//   reg j, half h: row' = (lane>>2) + 8*(j&1), k' = (lane&3)*2 + 8*(j>>1) + h
// B image: [nbp(4)][kb16(2)][lane(32)][j(4)] uint32;
//   nb = nbp*2 + (j>>1), r = j&1: k = r*8 + (lane&3)*2 + h, n = nb*8 + (lane>>2)
// ---------------------------------------------------------------------------
__device__ uint32_t g_xp[(long)TT * 2 * XKT * A_IMG];
__device__ uint32_t g_hp[2][2 * 32 * A_IMG];
__device__ uint32_t g_Wp[(long)64 * NKT * B_IMG];
__device__ float    g_c[BB * HH];

__device__ __forceinline__ float sigf(float x) { return 1.0f / (1.0f + expf(-x)); }

// ---------------------------------------------------------------------------
// Column permutation: permuted col n -> gate = (n>>3)&3,
//   hcol = ((n>>6)<<4) | (((n>>5)&1)<<3) | (n&7)
// ---------------------------------------------------------------------------
__global__ void transform_x(const float* __restrict__ x) {
    uint32_t p = blockIdx.x * blockDim.x + threadIdx.x;   // 8,388,608 total
    int j    = p & 3;
    int lane = (p >> 2) & 31;
    int kb   = (p >> 7) & 1;
    int mb   = (p >> 8) & 7;
    int kt   = (p >> 11) & 7;
    int mt   = (p >> 14) & 1;
    int t    = p >> 15;
    int rowp = (lane >> 2) + 8 * (j & 1);
    int kp   = (lane & 3) * 2 + 8 * (j >> 1);
    int b    = mt * 128 + mb * 16 + rowp;
    int i    = kt * 32 + kb * 16 + kp;
    const float* src = x + ((long)b * TT + t) * II + i;
    __half2 v = __floats2half2_rn(src[0], src[1]);
    g_xp[p] = *(uint32_t*)&v;
}

__global__ void transform_W(const float* __restrict__ Wx, const float* __restrict__ Wh) {
    uint32_t p = blockIdx.x * blockDim.x + threadIdx.x;
    if (p >= (uint32_t)64 * NKT * B_IMG) return;
    int j    = p & 3;
    int lane = (p >> 2) & 31;
    int kb   = (p >> 7) & 1;
    int nbp  = (p >> 8) & 3;
    int kt   = (int)((p >> 10) % NKT);
    int ctan = (int)((p >> 10) / NKT);
    int nb   = nbp * 2 + (j >> 1);
    int r    = j & 1;
    int n    = ctan * 64 + nb * 8 + (lane >> 2);
    int gate = (n >> 3) & 3;
    int hcol = ((n >> 6) << 4) | (((n >> 5) & 1) << 3) | (n & 7);
    int col  = gate * HH + hcol;
    int kg   = kt * 32 + kb * 16 + r * 8 + (lane & 3) * 2;
    float v0 = (kg < II)     ? Wx[(long)kg * NG + col]       : Wh[(long)(kg - II) * NG + col];
    float v1 = (kg + 1 < II) ? Wx[(long)(kg + 1) * NG + col] : Wh[(long)(kg + 1 - II) * NG + col];
    __half2 v = __floats2half2_rn(v0, v1);
    g_Wp[p] = *(uint32_t*)&v;
}

__global__ void init_state(const float* __restrict__ h0, const float* __restrict__ c0) {
    uint32_t p = blockIdx.x * blockDim.x + threadIdx.x;
    if (p >= 262144) return;
    if (p < 131072) {   // h0 -> packed A images
        int j    = p & 3;
        int lane = (p >> 2) & 31;
        int kb   = (p >> 7) & 1;
        int mb   = (p >> 8) & 7;
        int hkt  = (p >> 11) & 31;
        int mt   = (p >> 16) & 1;
        int rowp = (lane >> 2) + 8 * (j & 1);
        int kp   = (lane & 3) * 2 + 8 * (j >> 1);
        int b    = mt * 128 + mb * 16 + rowp;
        int hc   = hkt * 32 + kb * 16 + kp;
        __half2 v = __floats2half2_rn(h0[b * HH + hc], h0[b * HH + hc + 1]);
        g_hp[0][p] = *(uint32_t*)&v;
    }
    g_c[p] = c0[p];
}

// ---------------------------------------------------------------------------
__device__ __forceinline__ void cp16(uint32_t saddr, const void* g) {
    asm volatile("cp.async.cg.shared.global [%0], [%1], 16;\n" :: "r"(saddr), "l"(g));
}
#define CP_COMMIT() asm volatile("cp.async.commit_group;\n" ::: "memory")
#define CP_WAIT(N)  asm volatile("cp.async.wait_group %0;\n" :: "n"(N) : "memory")

__device__ __forceinline__ void mma16816(float* d, const uint4& a, uint32_t b0, uint32_t b1) {
    asm volatile(
        "mma.sync.aligned.m16n8k16.row.col.f32.f16.f16.f32 "
        "{%0,%1,%2,%3}, {%4,%5,%6,%7}, {%8,%9}, {%0,%1,%2,%3};"
        : "+f"(d[0]), "+f"(d[1]), "+f"(d[2]), "+f"(d[3])
        : "r"(a.x), "r"(a.y), "r"(a.z), "r"(a.w), "r"(b0), "r"(b1));
}

// ---------------------------------------------------------------------------
// Per-step fused kernel. 4-stage (BK=64) cp.async pipeline, 20 barriers.
// ---------------------------------------------------------------------------
__global__ void __launch_bounds__(512, 1)
lstm_step(const float* __restrict__ bias,   // (4H,)
          float* __restrict__ out,          // outputs | hN | cN
          int t, int srcbuf)
{
    extern __shared__ uint4 smem[];
    uint4* sA4 = smem;                      // [4][1024] uint4 (16KB/stage)
    uint4* sB4 = smem + STAGES * 1024;      // [4][512]  uint4 (8KB/stage)

    const uint32_t* __restrict__ hsrc = g_hp[srcbuf];
    uint32_t*       __restrict__ hdst = g_hp[srcbuf ^ 1];

    const int tid    = threadIdx.x;
    const int lane   = tid & 31;
    const int warp   = tid >> 5;
    const int warp_m = warp >> 1;        // 0..7
    const int warp_n = warp & 1;         // 0..1
    const int ctan   = blockIdx.x;       // 0..63
    const int mt     = blockIdx.y;       // 0..1

    const uint32_t sA_b = (uint32_t)__cvta_generic_to_shared(sA4);
    const uint32_t sB_b = (uint32_t)__cvta_generic_to_shared(sB4);

    // columns this thread owns: hbase, hbase+1 (for all 4 gates)
    const int hbase = ctan * 16 + warp_n * 8 + 2 * (lane & 3);

    float acc[4][4];
    #pragma unroll
    for (int g = 0; g < 4; g++) {
        float b0 = __ldg(bias + g * HH + hbase);
        float b1 = __ldg(bias + g * HH + hbase + 1);
        acc[g][0] = b0; acc[g][1] = b1; acc[g][2] = b0; acc[g][3] = b1;
    }

    // stage loader: linear copy of two consecutive 32-k images (A 2/thr, B 1/thr)
    auto issue = [&](int st) {
        int s = st & (STAGES - 1);
        const uint32_t* asrc = (st < XST)
            ? g_xp + ((long)(t * 2 + mt) * XKT + st * 2) * A_IMG
            : hsrc + (long)(mt * 32 + (st - XST) * 2) * A_IMG;
        const uint32_t* bsrc = g_Wp + ((long)ctan * NKT + st * 2) * B_IMG;
        cp16(sA_b + (uint32_t)(s * 1024 + tid) * 16, asrc + tid * 4);
        cp16(sA_b + (uint32_t)(s * 1024 + tid + 512) * 16, asrc + (tid + 512) * 4);
        cp16(sB_b + (uint32_t)(s * 512 + tid) * 16, bsrc + tid * 4);
    };

    issue(0); CP_COMMIT();
    issue(1); CP_COMMIT();
    issue(2); CP_COMMIT();

    for (int st = 0; st < NST; st++) {
        CP_WAIT(2);
        __syncthreads();

        int s = st & (STAGES - 1);
        const uint4* A = sA4 + s * 1024;
        const uint4* Bm = sB4 + s * 512;

        // preload ALL stage fragments (6 LDS.128 groups in flight), then 16 MMAs
        uint4 af[4];
        uint4 bf[8];
        #pragma unroll
        for (int kk = 0; kk < 4; kk++)
            af[kk] = A[(kk >> 1) * 512 + (warp_m * 2 + (kk & 1)) * 32 + lane];
        #pragma unroll
        for (int kk = 0; kk < 4; kk++) {
            #pragma unroll
            for (int np = 0; np < 2; np++)
                bf[kk * 2 + np] =
                    Bm[(kk >> 1) * 256 + ((warp_n * 2 + np) * 2 + (kk & 1)) * 32 + lane];
        }
        #pragma unroll
        for (int kk = 0; kk < 4; kk++) {
            mma16816(acc[0], af[kk], bf[kk * 2].x,     bf[kk * 2].y);
            mma16816(acc[1], af[kk], bf[kk * 2].z,     bf[kk * 2].w);
            mma16816(acc[2], af[kk], bf[kk * 2 + 1].x, bf[kk * 2 + 1].y);
            mma16816(acc[3], af[kk], bf[kk * 2 + 1].z, bf[kk * 2 + 1].w);
        }

        if (st + 3 < NST) issue(st + 3);   // stage (st-1)&3: readers passed barrier above
        CP_COMMIT();
    }

    // ---- epilogue (identical to round 5) ------------------------------------
    #pragma unroll
    for (int half = 0; half < 2; half++) {
        int m_loc = warp_m * 16 + (lane >> 2) + half * 8;
        int r = mt * 128 + m_loc;
        long cidx = (long)r * HH + hbase;
        float2 cold = *(const float2*)(g_c + cidx);
        float hn[2], cn[2];
        #pragma unroll
        for (int j = 0; j < 2; j++) {
            int c2 = half * 2 + j;
            float ii = sigf(acc[0][c2]);
            float ff = sigf(acc[1][c2]);
            float tg = tanhf(acc[2][c2]);
            float oo = sigf(acc[3][c2]);
            float cnew = ff * (j ? cold.y : cold.x) + ii * tg;
            cn[j] = cnew;
            hn[j] = oo * tanhf(cnew);
        }
        *(float2*)(g_c + cidx) = make_float2(cn[0], cn[1]);
        *(float2*)(out + ((long)r * TT + t) * HH + hbase) = make_float2(hn[0], hn[1]);
        if (t == TT - 1) {
            *(float2*)(out + BTH + (long)r * HH + hbase)      = make_float2(hn[0], hn[1]);
            *(float2*)(out + BTH + BH + (long)r * HH + hbase) = make_float2(cn[0], cn[1]);
        }
        float h0s = hn[0], h1s = hn[1];
        if (hbase == 0) {
            h0s = hn[0] + TAUc * (MHUc * hn[0] + hn[1] / MHUc);
            h1s = hn[1] - TAUc * (MHUc * hn[0]);
        }
        int mb   = m_loc >> 4;
        int rowp = m_loc & 15;
        int hkt  = hbase >> 5;
        int kb   = (hbase >> 4) & 1;
        int jj   = ((rowp >> 3) & 1) | ((((hbase & 15) >= 8) ? 1 : 0) << 1);
        int lanep = ((rowp & 7) << 2) | ((hbase & 7) >> 1);
        __half2 hv = __floats2half2_rn(h0s, h1s);
        hdst[(long)(mt * 32 + hkt) * A_IMG + ((mb * 2 + kb) * 32 + lanep) * 4 + jj] =
            *(uint32_t*)&hv;
    }
}

// ---------------------------------------------------------------------------
extern "C" void kernel_launch(void* const* d_in, const int* in_sizes, int n_in,
                              void* d_out, int out_size) {
    const float* x  = (const float*)d_in[0];
    const float* h0 = (const float*)d_in[1];
    const float* c0 = (const float*)d_in[2];
    const float* Wx = (const float*)d_in[3];
    const float* Wh = (const float*)d_in[4];
    const float* b  = (const float*)d_in[5];
    float* out = (float*)d_out;

    cudaFuncSetAttribute(lstm_step, cudaFuncAttributeMaxDynamicSharedMemorySize, DSMEM);

    transform_x<<<32768, 256>>>(x);
    {
        long total = (long)64 * NKT * B_IMG;
        transform_W<<<(int)((total + 255) / 256), 256>>>(Wx, Wh);
    }
    init_state<<<1024, 256>>>(h0, c0);

    for (int t = 0; t < TT; t++) {
        lstm_step<<<dim3(64, 2), 512, DSMEM>>>(b, out, t, t & 1);
    }
}